// round 8
// baseline (speedup 1.0000x reference)
#include <cuda_runtime.h>
#include <math.h>

// WaveNet collapsed to the last-sample 32-dim recurrence (k=0 tap only):
//   u_L = tanh(F_L x) * sigmoid(G_L x);  x = (R_L + I) u;  skip += S_L u
//   out = end2 @ relu(end1 @ relu(skip) + b1) + b2
//
// R8: split by data locality so no SM pulls >0.5MB through L1.
//   wn_pack : repack weights (F'=-2F, G'=-G, R'=R+I), transposed skip/end1.
//   wn_rec  : grid=8 (batch). Serial recurrence + smem weight ring
//             (reg-batched producers). Writes u[8][1280] to global.
//   wn_skip : grid=8 (channel-group). 32 channels x 8 batches; skipT slice
//             read ONCE per block (160KB). Also emits partial end1 products.
//   wn_fin  : grid=8 (batch). Sum partials + bias, relu, end2 dot.

#define NL   40
#define RC   32
#define SC   256
#define CIN  6
#define T_IN 8192
#define FULLM 0xffffffffu

#define CH   4                 // layers per chunk
#define NCH  (NL / CH)         // 10 chunks
#define LW   768               // float4 per layer (3072 floats: F@0 G@256 R@512)
#define CW   (CH * LW)         // float4 per chunk = 3072
#define RING_BYTES (2 * CW * 16)   // 98304

typedef unsigned long long u64;

__device__ float g_pk[NL * 3072];            // packed F'/G'/R', 491 KB
__device__ float g_skipT4[(NL * RC) * SC];   // [kg][c][4kk], 1.31 MB
__device__ float g_end1T4[SC * SC];          // [jg][c][4jj], 256 KB
__device__ float g_xs0[8 * RC];
__device__ float g_us[8 * NL * RC];          // u activations, 40 KB
__device__ float g_e1p[8 * 8 * SC];          // end1 partials [cg][b][co]

__device__ __forceinline__ void fma2(u64& d, u64 a, u64 b) {
    asm("fma.rn.f32x2 %0, %1, %2, %3;" : "=l"(d) : "l"(a), "l"(b), "l"(d));
}
__device__ __forceinline__ void add2(u64& d, u64 a, u64 b) {
    asm("add.rn.f32x2 %0, %1, %2;" : "=l"(d) : "l"(a), "l"(b));
}
__device__ __forceinline__ float2 upk(u64 v) {
    float2 r; asm("mov.b64 {%0, %1}, %2;" : "=f"(r.x), "=f"(r.y) : "l"(v));
    return r;
}

// ---------------------------------------------------------------- pack
__global__ void wn_pack(const float* __restrict__ x,
                        const float* __restrict__ start_w,
                        const float* __restrict__ filter_w,
                        const float* __restrict__ gate_w,
                        const float* __restrict__ res_w,
                        const float* __restrict__ skip_w,
                        const float* __restrict__ end1_w)
{
    const int NA = NL * LW;            // 30720
    const int NB = NL * RC * SC / 4;   // 81920
    const int NC = SC * SC / 4;        // 16384
    const int total = NA + NB + NC + 8 * RC;

    for (int idx = blockIdx.x * blockDim.x + threadIdx.x; idx < total;
         idx += gridDim.x * blockDim.x) {
        if (idx < NA) {
            int L  = idx / LW;
            int r  = idx % LW;
            int sec = r >> 8;              // 0=F' 1=G' 2=R'
            int t  = r & 255;
            int jg = t >> 5;
            int i  = t & 31;
            float4 o;
            if (sec < 2) {
                const float* src = (sec ? gate_w : filter_w)
                                   + L * 2048 + i * 64 + 8 * jg;
                const float4 a = *(const float4*)src;
                const float4 c = *(const float4*)(src + 4);
                const float sc = sec ? -1.f : -2.f;
                o.x = sc * a.x; o.y = sc * a.z; o.z = sc * c.x; o.w = sc * c.z;
            } else {
                o = *(const float4*)(res_w + L * 1024 + i * 32 + 4 * jg);
                if ((i >> 2) == jg) (&o.x)[i & 3] += 1.f;   // bake identity
            }
            ((float4*)g_pk)[idx] = o;
        } else if (idx < NA + NB) {
            int t  = idx - NA;
            int kg = t >> 8;
            int c  = t & 255;
            int L  = kg >> 3;
            int j0 = (kg & 7) * 4;
            ((float4*)g_skipT4)[t] =
                *(const float4*)(skip_w + L * (SC * RC) + c * RC + j0);
        } else if (idx < NA + NB + NC) {
            int t  = idx - NA - NB;
            int jg = t >> 8;
            int c  = t & 255;
            ((float4*)g_end1T4)[t] = *(const float4*)(end1_w + c * SC + 4 * jg);
        } else {
            int t = idx - NA - NB - NC;
            int b = t / RC, i = t % RC;
            float s = 0.f;
            #pragma unroll
            for (int ci = 0; ci < CIN; ci++)
                s += start_w[i * CIN + ci] * x[(b * CIN + ci) * T_IN + (T_IN - 1)];
            g_xs0[b * RC + i] = s;
        }
    }
}

// ---------------------------------------------------------------- rec
extern __shared__ float ring[];    // RING_BYTES dynamic smem

__global__ __launch_bounds__(256, 1)
void wn_rec()
{
    const int b    = blockIdx.x;
    const int tid  = threadIdx.x;
    const int lane = tid & 31;
    const int warp = tid >> 5;

    __shared__ __align__(16) float xs[RC];
    __shared__ __align__(16) float uc[RC];

    // prologue: batched copy of chunk 0 (12 float4 each, exact)
    {
        const float4* src = (const float4*)g_pk;
        float4*       dst = (float4*)ring;
        float4 t[12];
        #pragma unroll
        for (int k = 0; k < 12; k++) t[k] = src[tid + 256 * k];
        #pragma unroll
        for (int k = 0; k < 12; k++) dst[tid + 256 * k] = t[k];
    }
    if (warp == 0) xs[lane] = g_xs0[b * RC + lane];
    __syncthreads();

    for (int q = 0; q < NCH; q++) {
        if (warp == 0) {
            const float4* wc = (const float4*)ring + (q & 1) * CW;
            #pragma unroll
            for (int l = 0; l < CH; l++) {
                const int L = q * CH + l;
                const float4* wl = wc + l * LW + lane;

                // phase A: f'/g' GEMV (F'=-2F, G'=-G baked in)
                u64 fa = 0ull, fb = 0ull, ga = 0ull, gb = 0ull;
                #pragma unroll
                for (int jg = 0; jg < 8; jg++) {
                    const ulonglong2 xv = *(const ulonglong2*)&xs[4 * jg];
                    const ulonglong2 Fw = *(const ulonglong2*)(wl + jg * 32);
                    const ulonglong2 Gw = *(const ulonglong2*)(wl + 256 + jg * 32);
                    fma2(fa, Fw.x, xv.x); fma2(fb, Fw.y, xv.y);
                    fma2(ga, Gw.x, xv.x); fma2(gb, Gw.y, xv.y);
                }
                add2(fa, fa, fb);
                add2(ga, ga, gb);
                const float2 fp = upk(fa);
                const float2 gp = upk(ga);
                const float e1 = __expf(fp.x + fp.y);   // e^{-2f}
                const float e2 = __expf(gp.x + gp.y);   // e^{-g}
                // u = tanh(f)*sig(g) = (1-e1) / ((1+e1)(1+e2))
                const float den = (1.f + e1) * (1.f + e2);
                const float u   = __fdividef(1.f - e1, den);
                uc[lane] = u;
                g_us[b * (NL * RC) + L * RC + lane] = u;
                __syncwarp();

                // phase B: x = (R+I) u
                u64 ra = 0ull, rb = 0ull;
                #pragma unroll
                for (int jg = 0; jg < 8; jg++) {
                    const ulonglong2 uv = *(const ulonglong2*)&uc[4 * jg];
                    const ulonglong2 Rw = *(const ulonglong2*)(wl + 512 + jg * 32);
                    fma2(ra, Rw.x, uv.x); fma2(rb, Rw.y, uv.y);
                }
                add2(ra, ra, rb);
                const float2 rp = upk(ra);
                xs[lane] = rp.x + rp.y;
                __syncwarp();
            }
        } else if (q + 1 < NCH) {
            // producers: batched stage of chunk q+1 into the other ring slot
            const float4* src = (const float4*)g_pk + (q + 1) * CW;
            float4*       dst = (float4*)ring + ((q + 1) & 1) * CW;
            const int t0 = tid - 32;           // 0..223
            float4 t[14];
            #pragma unroll
            for (int k = 0; k < 14; k++) {
                const int i = t0 + 224 * k;
                if (i < CW) t[k] = src[i];
            }
            #pragma unroll
            for (int k = 0; k < 14; k++) {
                const int i = t0 + 224 * k;
                if (i < CW) dst[i] = t[k];
            }
        }
        __syncthreads();
    }
}

// ---------------------------------------------------------------- skip
// grid = 8 channel-groups; warp = batch, lane = local channel.
__global__ __launch_bounds__(256, 1)
void wn_skip()
{
    const int cg   = blockIdx.x;
    const int tid  = threadIdx.x;
    const int lane = tid & 31;
    const int b    = tid >> 5;          // warp = batch

    __shared__ __align__(16) float us[8 * NL * RC];   // 40 KB
    __shared__ __align__(16) float hsl[8][RC];

    // stage all u (coalesced, 10 float4/thread)
    {
        const float4* src = (const float4*)g_us;
        float4*       dst = (float4*)us;
        #pragma unroll
        for (int k = 0; k < 10; k++) dst[tid + 256 * k] = src[tid + 256 * k];
    }
    __syncthreads();

    // skip GEMV: channel c = 32*cg + lane, K = 1280
    {
        float acc = 0.f;
        const float4* sp = (const float4*)g_skipT4 + 32 * cg + lane;
        const float4* up = (const float4*)(us + b * (NL * RC));
        #pragma unroll 8
        for (int kg = 0; kg < 320; kg++) {
            const float4 s4 = sp[kg * 256];
            const float4 u4 = up[kg];
            acc = fmaf(s4.x, u4.x, fmaf(s4.y, u4.y,
                  fmaf(s4.z, u4.z, fmaf(s4.w, u4.w, acc))));
        }
        hsl[b][lane] = fmaxf(acc, 0.f);
    }
    __syncthreads();

    // partial end1: part[cg][b][co] = sum_{ci in this cg} E1[co][ci] h[ci]
    {
        const float4* ep = (const float4*)g_end1T4;
        float* outp = g_e1p + (cg * 8 + b) * SC;
        #pragma unroll
        for (int m = 0; m < 8; m++) {
            const int co = lane + 32 * m;
            float e = 0.f;
            #pragma unroll
            for (int jg = 0; jg < 8; jg++) {
                const float4 a4 = ep[(8 * cg + jg) * 256 + co];
                const float4 h4 = *reinterpret_cast<const float4*>(&hsl[b][4 * jg]);
                e = fmaf(a4.x, h4.x, fmaf(a4.y, h4.y,
                    fmaf(a4.z, h4.z, fmaf(a4.w, h4.w, e))));
            }
            outp[co] = e;
        }
    }
}

// ---------------------------------------------------------------- fin
__global__ __launch_bounds__(256, 1)
void wn_fin(const float* __restrict__ end1_b,
            const float* __restrict__ end2_w,
            const float* __restrict__ end2_b,
            float* __restrict__ out)
{
    const int b    = blockIdx.x;
    const int tid  = threadIdx.x;
    const int lane = tid & 31;
    const int warp = tid >> 5;

    __shared__ float red8[8];

    float e = end1_b[tid];
    #pragma unroll
    for (int cg = 0; cg < 8; cg++) e += g_e1p[(cg * 8 + b) * SC + tid];
    e = fmaxf(e, 0.f);

    float o = end2_w[tid] * e;
    #pragma unroll
    for (int off = 16; off > 0; off >>= 1)
        o += __shfl_xor_sync(FULLM, o, off);
    if (lane == 0) red8[warp] = o;
    __syncthreads();
    if (tid == 0) {
        float tot = 0.f;
        #pragma unroll
        for (int w = 0; w < 8; w++) tot += red8[w];
        out[b] = tot + end2_b[0];
    }
}

extern "C" void kernel_launch(void* const* d_in, const int* in_sizes, int n_in,
                              void* d_out, int out_size)
{
    const float* x        = (const float*)d_in[0];
    const float* start_w  = (const float*)d_in[1];
    const float* filter_w = (const float*)d_in[2];
    const float* gate_w   = (const float*)d_in[3];
    const float* res_w    = (const float*)d_in[4];
    const float* skip_w   = (const float*)d_in[5];
    const float* end1_w   = (const float*)d_in[6];
    const float* end1_b   = (const float*)d_in[7];
    const float* end2_w   = (const float*)d_in[8];
    const float* end2_b   = (const float*)d_in[9];
    float* out = (float*)d_out;

    cudaFuncSetAttribute(wn_rec,
                         cudaFuncAttributeMaxDynamicSharedMemorySize,
                         RING_BYTES);

    wn_pack<<<253, 512>>>(x, start_w, filter_w, gate_w, res_w, skip_w, end1_w);
    wn_rec<<<8, 256, RING_BYTES>>>();
    wn_skip<<<8, 256>>>();
    wn_fin<<<8, 256>>>(end1_b, end2_w, end2_b, out);
}